// round 1
// baseline (speedup 1.0000x reference)
#include <cuda_runtime.h>
#include <math.h>

#define B_    8
#define SEQ   8192
#define DIM   512
#define HEADS 8
#define HD    64
#define FF_   2048
#define WIN   128
#define TD    512
#define NTOK  (B_*SEQ)        // 65536
#define NW    (SEQ/WIN)       // 64

// ---------------- scratch (device globals; no runtime allocation) ----------
__device__ float g_ss  [B_ * 2 * DIM];            // adaLN scale/shift
__device__ float g_xn  [(size_t)NTOK * DIM];      // x_norm / h2 (reused)
__device__ float g_qkv [(size_t)NTOK * 3 * DIM];  // qkv
__device__ float g_attn[(size_t)NTOK * DIM];      // attention output (B,N,C)
__device__ float g_y   [(size_t)NTOK * DIM];      // x + proj(attn)
__device__ float g_ff  [(size_t)NTOK * FF_];      // gelu(h2 @ w1 + b1)

// ---------------- kernel 1: ss = silu(t_emb) @ time_w + time_b -------------
__global__ void time_mlp_kernel(const float* __restrict__ te,
                                const float* __restrict__ tw,
                                const float* __restrict__ tb) {
    __shared__ float st[TD];
    int b = blockIdx.y;
    for (int k = threadIdx.x; k < TD; k += blockDim.x) {
        float v = te[b * TD + k];
        st[k] = v / (1.f + __expf(-v));
    }
    __syncthreads();
    int j = blockIdx.x * blockDim.x + threadIdx.x;   // 0..1023
    float acc = tb[j];
    for (int k = 0; k < TD; k++)
        acc = fmaf(st[k], tw[k * (2 * DIM) + j], acc);
    g_ss[b * 2 * DIM + j] = acc;
}

// ---------------- kernel 2: LayerNorm (optionally adaLN-modulated) ---------
template <int MOD>
__global__ void ln_kernel(const float* __restrict__ x,
                          const float* __restrict__ gam,
                          const float* __restrict__ bet,
                          float* __restrict__ out) {
    int row  = blockIdx.x;
    int t    = threadIdx.x;           // 128 threads, 4 floats each
    int lane = t & 31, wid = t >> 5;
    float4 xv = ((const float4*)(x + (size_t)row * DIM))[t];
    float s  = xv.x + xv.y + xv.z + xv.w;
    float s2 = fmaf(xv.x, xv.x, fmaf(xv.y, xv.y, fmaf(xv.z, xv.z, xv.w * xv.w)));
    #pragma unroll
    for (int o = 16; o > 0; o >>= 1) {
        s  += __shfl_xor_sync(0xffffffffu, s,  o);
        s2 += __shfl_xor_sync(0xffffffffu, s2, o);
    }
    __shared__ float red[8];
    if (lane == 0) { red[wid] = s; red[4 + wid] = s2; }
    __syncthreads();
    s  = red[0] + red[1] + red[2] + red[3];
    s2 = red[4] + red[5] + red[6] + red[7];
    float mu   = s * (1.f / DIM);
    float var  = s2 * (1.f / DIM) - mu * mu;
    float rstd = rsqrtf(var + 1e-5f);

    float4 gg = ((const float4*)gam)[t];
    float4 bb = ((const float4*)bet)[t];
    float4 o;
    o.x = (xv.x - mu) * rstd * gg.x + bb.x;
    o.y = (xv.y - mu) * rstd * gg.y + bb.y;
    o.z = (xv.z - mu) * rstd * gg.z + bb.z;
    o.w = (xv.w - mu) * rstd * gg.w + bb.w;
    if (MOD) {
        int b = row >> 13;            // row / SEQ
        float4 sc = ((const float4*)(g_ss + b * 2 * DIM))[t];
        float4 sh = ((const float4*)(g_ss + b * 2 * DIM + DIM))[t];
        o.x = o.x * (1.f + sc.x) + sh.x;
        o.y = o.y * (1.f + sc.y) + sh.y;
        o.z = o.z * (1.f + sc.z) + sh.z;
        o.w = o.w * (1.f + sc.w) + sh.w;
    }
    ((float4*)(out + (size_t)row * DIM))[t] = o;
}

// ---------------- kernel 3: generic fp32 GEMM, C = A@W + bias [+res|gelu] --
// EPI: 0 = bias only, 1 = bias + residual, 2 = bias + exact GELU
template <int EPI>
__global__ __launch_bounds__(256)
void gemm_kernel(const float* __restrict__ A, const float* __restrict__ W,
                 const float* __restrict__ bias, const float* __restrict__ res,
                 float* __restrict__ C, int K, int N) {
    __shared__ float As[16][132];
    __shared__ float Bs[16][128];
    int bm = blockIdx.y * 128, bn = blockIdx.x * 128;
    int tid = threadIdx.x;
    int tx = tid & 15, ty = tid >> 4;
    float acc[8][8];
    #pragma unroll
    for (int i = 0; i < 8; i++)
        #pragma unroll
        for (int j = 0; j < 8; j++) acc[i][j] = 0.f;

    int arow = tid >> 2, ak4 = tid & 3;       // A: rows arow, arow+64
    int bk = tid >> 5, bn4 = tid & 31;        // B: k rows bk, bk+8

    for (int k0 = 0; k0 < K; k0 += 16) {
        __syncthreads();
        #pragma unroll
        for (int i = 0; i < 2; i++) {
            int r = arow + 64 * i;
            float4 a4 = *(const float4*)(A + (size_t)(bm + r) * K + k0 + ak4 * 4);
            As[ak4 * 4 + 0][r] = a4.x;
            As[ak4 * 4 + 1][r] = a4.y;
            As[ak4 * 4 + 2][r] = a4.z;
            As[ak4 * 4 + 3][r] = a4.w;
        }
        #pragma unroll
        for (int i = 0; i < 2; i++) {
            int kk = bk + 8 * i;
            *(float4*)&Bs[kk][bn4 * 4] =
                *(const float4*)(W + (size_t)(k0 + kk) * N + bn + bn4 * 4);
        }
        __syncthreads();
        #pragma unroll
        for (int kk = 0; kk < 16; kk++) {
            float ra[8], rb[8];
            float4 a0 = *(float4*)&As[kk][ty * 8];
            float4 a1 = *(float4*)&As[kk][ty * 8 + 4];
            float4 b0 = *(float4*)&Bs[kk][tx * 8];
            float4 b1 = *(float4*)&Bs[kk][tx * 8 + 4];
            ra[0]=a0.x; ra[1]=a0.y; ra[2]=a0.z; ra[3]=a0.w;
            ra[4]=a1.x; ra[5]=a1.y; ra[6]=a1.z; ra[7]=a1.w;
            rb[0]=b0.x; rb[1]=b0.y; rb[2]=b0.z; rb[3]=b0.w;
            rb[4]=b1.x; rb[5]=b1.y; rb[6]=b1.z; rb[7]=b1.w;
            #pragma unroll
            for (int i = 0; i < 8; i++)
                #pragma unroll
                for (int j = 0; j < 8; j++)
                    acc[i][j] = fmaf(ra[i], rb[j], acc[i][j]);
        }
    }

    #pragma unroll
    for (int i = 0; i < 8; i++) {
        int row = bm + ty * 8 + i;
        #pragma unroll
        for (int j = 0; j < 8; j += 4) {
            int col = bn + tx * 8 + j;
            float4 bi = *(const float4*)(bias + col);
            float4 o;
            o.x = acc[i][j + 0] + bi.x;
            o.y = acc[i][j + 1] + bi.y;
            o.z = acc[i][j + 2] + bi.z;
            o.w = acc[i][j + 3] + bi.w;
            if (EPI == 1) {
                float4 rr = *(const float4*)(res + (size_t)row * N + col);
                o.x += rr.x; o.y += rr.y; o.z += rr.z; o.w += rr.w;
            } else if (EPI == 2) {
                o.x = 0.5f * o.x * (1.f + erff(o.x * 0.70710678118654752f));
                o.y = 0.5f * o.y * (1.f + erff(o.y * 0.70710678118654752f));
                o.z = 0.5f * o.z * (1.f + erff(o.z * 0.70710678118654752f));
                o.w = 0.5f * o.w * (1.f + erff(o.w * 0.70710678118654752f));
            }
            *(float4*)(C + (size_t)row * N + col) = o;
        }
    }
}

// ---------------- kernel 4: local windowed attention -----------------------
// grid (NW, HEADS, B_), 128 threads; thread r = query row r of the window.
// Flash-style online softmax over the <=3 valid context windows.
__global__ __launch_bounds__(128)
void attn_kernel(const float* __restrict__ qkv, float* __restrict__ out) {
    extern __shared__ float sm[];
    float* Ks   = sm;                 // 128*64
    float* Vs   = sm + 128 * 64;      // 128*64
    float* Srow = sm + 2 * 128 * 64;  // 128*129

    int w = blockIdx.x, h = blockIdx.y, b = blockIdx.z;
    int r = threadIdx.x;

    const float scale = 0.125f;       // 1/sqrt(64)
    int qtok = b * SEQ + w * WIN + r;
    const float* qptr = qkv + (size_t)qtok * (3 * DIM) + h * HD;

    float q[HD];
    #pragma unroll
    for (int d4 = 0; d4 < HD / 4; d4++) {
        float4 v4 = ((const float4*)qptr)[d4];
        q[4 * d4 + 0] = v4.x * scale;
        q[4 * d4 + 1] = v4.y * scale;
        q[4 * d4 + 2] = v4.z * scale;
        q[4 * d4 + 3] = v4.w * scale;
    }

    float acc[HD];
    #pragma unroll
    for (int d = 0; d < HD; d++) acc[d] = 0.f;
    float m = -1e30f, l = 0.f;

    #pragma unroll
    for (int dw = -1; dw <= 1; dw++) {
        int wi = w + dw;
        if (wi < 0 || wi >= NW) continue;
        __syncthreads();   // previous window fully consumed
        {
            int ktok = b * SEQ + wi * WIN + r;
            const float* kp = qkv + (size_t)ktok * (3 * DIM) + DIM     + h * HD;
            const float* vp = qkv + (size_t)ktok * (3 * DIM) + 2 * DIM + h * HD;
            #pragma unroll
            for (int d4 = 0; d4 < HD / 4; d4++) {
                ((float4*)(Ks + r * HD))[d4] = ((const float4*)kp)[d4];
                ((float4*)(Vs + r * HD))[d4] = ((const float4*)vp)[d4];
            }
        }
        __syncthreads();

        float wmax = -1e30f;
        for (int j = 0; j < WIN; j++) {
            const float4* K4 = (const float4*)(Ks + j * HD);
            float s = 0.f;
            #pragma unroll
            for (int d4 = 0; d4 < HD / 4; d4++) {
                float4 kv = K4[d4];
                s = fmaf(q[4 * d4 + 0], kv.x, s);
                s = fmaf(q[4 * d4 + 1], kv.y, s);
                s = fmaf(q[4 * d4 + 2], kv.z, s);
                s = fmaf(q[4 * d4 + 3], kv.w, s);
            }
            Srow[r * 129 + j] = s;
            wmax = fmaxf(wmax, s);
        }
        float mnew = fmaxf(m, wmax);
        float corr = __expf(m - mnew);
        #pragma unroll
        for (int d = 0; d < HD; d++) acc[d] *= corr;
        l *= corr;
        for (int j = 0; j < WIN; j++) {
            float p = __expf(Srow[r * 129 + j] - mnew);
            l += p;
            const float4* V4 = (const float4*)(Vs + j * HD);
            #pragma unroll
            for (int d4 = 0; d4 < HD / 4; d4++) {
                float4 vv = V4[d4];
                acc[4 * d4 + 0] = fmaf(p, vv.x, acc[4 * d4 + 0]);
                acc[4 * d4 + 1] = fmaf(p, vv.y, acc[4 * d4 + 1]);
                acc[4 * d4 + 2] = fmaf(p, vv.z, acc[4 * d4 + 2]);
                acc[4 * d4 + 3] = fmaf(p, vv.w, acc[4 * d4 + 3]);
            }
        }
        m = mnew;
    }

    float inv = 1.f / l;
    float* op = out + (size_t)qtok * DIM + h * HD;
    #pragma unroll
    for (int d4 = 0; d4 < HD / 4; d4++) {
        float4 o;
        o.x = acc[4 * d4 + 0] * inv;
        o.y = acc[4 * d4 + 1] * inv;
        o.z = acc[4 * d4 + 2] * inv;
        o.w = acc[4 * d4 + 3] * inv;
        ((float4*)op)[d4] = o;
    }
}

// ---------------- host orchestration ---------------------------------------
extern "C" void kernel_launch(void* const* d_in, const int* in_sizes, int n_in,
                              void* d_out, int out_size) {
    const float* x      = (const float*)d_in[0];
    const float* t_emb  = (const float*)d_in[1];
    const float* ln1_g  = (const float*)d_in[2];
    const float* ln1_b  = (const float*)d_in[3];
    const float* qkv_w  = (const float*)d_in[4];
    const float* qkv_b  = (const float*)d_in[5];
    const float* proj_w = (const float*)d_in[6];
    const float* proj_b = (const float*)d_in[7];
    const float* ln2_g  = (const float*)d_in[8];
    const float* ln2_b  = (const float*)d_in[9];
    const float* mlp_w1 = (const float*)d_in[10];
    const float* mlp_b1 = (const float*)d_in[11];
    const float* mlp_w2 = (const float*)d_in[12];
    const float* mlp_b2 = (const float*)d_in[13];
    const float* time_w = (const float*)d_in[14];
    const float* time_b = (const float*)d_in[15];
    float* out = (float*)d_out;

    void* p;
    cudaGetSymbolAddress(&p, g_xn);   float* xn   = (float*)p;
    cudaGetSymbolAddress(&p, g_qkv);  float* qkv  = (float*)p;
    cudaGetSymbolAddress(&p, g_attn); float* attn = (float*)p;
    cudaGetSymbolAddress(&p, g_y);    float* y    = (float*)p;
    cudaGetSymbolAddress(&p, g_ff);   float* ff   = (float*)p;

    size_t attn_smem = (2 * 128 * 64 + 128 * 129) * sizeof(float); // 131584
    cudaFuncSetAttribute(attn_kernel, cudaFuncAttributeMaxDynamicSharedMemorySize,
                         (int)attn_smem);

    // 1. adaLN scale/shift
    time_mlp_kernel<<<dim3(2 * DIM / 256, B_), 256>>>(t_emb, time_w, time_b);
    // 2. modulated LN1
    ln_kernel<1><<<NTOK, 128>>>(x, ln1_g, ln1_b, xn);
    // 3. QKV GEMM  (65536 x 512) @ (512 x 1536)
    gemm_kernel<0><<<dim3(3 * DIM / 128, NTOK / 128), 256>>>(xn, qkv_w, qkv_b,
                                                             nullptr, qkv, DIM, 3 * DIM);
    // 4. local attention
    attn_kernel<<<dim3(NW, HEADS, B_), 128, attn_smem>>>(qkv, attn);
    // 5. proj + residual: y = x + attn @ proj_w + proj_b
    gemm_kernel<1><<<dim3(DIM / 128, NTOK / 128), 256>>>(attn, proj_w, proj_b,
                                                         x, y, DIM, DIM);
    // 6. LN2
    ln_kernel<0><<<NTOK, 128>>>(y, ln2_g, ln2_b, xn);
    // 7. MLP up + GELU
    gemm_kernel<2><<<dim3(FF_ / 128, NTOK / 128), 256>>>(xn, mlp_w1, mlp_b1,
                                                         nullptr, ff, DIM, FF_);
    // 8. MLP down + residual -> out
    gemm_kernel<1><<<dim3(DIM / 128, NTOK / 128), 256>>>(ff, mlp_w2, mlp_b2,
                                                         y, out, FF_, DIM);
}

// round 4
// speedup vs baseline: 2.0605x; 2.0605x over previous
#include <cuda_runtime.h>
#include <cuda_bf16.h>
#include <math.h>
#include <cstdint>

#define B_    8
#define SEQ   8192
#define DIM   512
#define HEADS 8
#define HD    64
#define FF_   2048
#define WIN   128
#define TD    512
#define NTOK  (B_*SEQ)        // 65536
#define NW    (SEQ/WIN)       // 64

// ---------------- scratch (device globals; no runtime allocation) ----------
__device__ float g_ss  [B_ * 2 * DIM];
__device__ float g_qkv [(size_t)NTOK * 3 * DIM];   // fp32 qkv
__device__ float g_y   [(size_t)NTOK * DIM];       // x + proj(attn), fp32
// hi/lo bf16 activations (GEMM A operands)
__device__ __nv_bfloat16 g_xh [(size_t)NTOK * DIM],  g_xl [(size_t)NTOK * DIM];
__device__ __nv_bfloat16 g_ah [(size_t)NTOK * DIM],  g_al [(size_t)NTOK * DIM];
__device__ __nv_bfloat16 g_fh [(size_t)NTOK * FF_],  g_fl [(size_t)NTOK * FF_];
// weights hi/lo, transposed to [N][K] bf16 (K contiguous)
__device__ __nv_bfloat16 g_wq_h[1536 * 512],  g_wq_l[1536 * 512];
__device__ __nv_bfloat16 g_wp_h[512 * 512],   g_wp_l[512 * 512];
__device__ __nv_bfloat16 g_w1_h[2048 * 512],  g_w1_l[2048 * 512];
__device__ __nv_bfloat16 g_w2_h[512 * 2048],  g_w2_l[512 * 2048];

// ---------------- PTX helpers ----------------------------------------------
__device__ __forceinline__ uint32_t smem_u32(const void* p) {
    uint32_t a;
    asm("{ .reg .u64 t; cvta.to.shared.u64 t, %1; cvt.u32.u64 %0, t; }"
        : "=r"(a) : "l"(p));
    return a;
}
__device__ __forceinline__ void cp16(uint32_t dst, const void* src) {
    asm volatile("cp.async.cg.shared.global [%0], [%1], 16;"
                 :: "r"(dst), "l"(src) : "memory");
}
#define CP_COMMIT() asm volatile("cp.async.commit_group;" ::: "memory")
#define CP_WAIT(n)  asm volatile("cp.async.wait_group %0;" :: "n"(n) : "memory")

__device__ __forceinline__ void ldsm4(uint32_t* r, uint32_t addr) {
    asm volatile("ldmatrix.sync.aligned.m8n8.x4.shared.b16 {%0,%1,%2,%3}, [%4];"
                 : "=r"(r[0]), "=r"(r[1]), "=r"(r[2]), "=r"(r[3]) : "r"(addr));
}
__device__ __forceinline__ void mma16816(float* d, const uint32_t* a,
                                         const uint32_t* b) {
    asm volatile(
        "mma.sync.aligned.m16n8k16.row.col.f32.bf16.bf16.f32 "
        "{%0,%1,%2,%3}, {%4,%5,%6,%7}, {%8,%9}, {%0,%1,%2,%3};"
        : "+f"(d[0]), "+f"(d[1]), "+f"(d[2]), "+f"(d[3])
        : "r"(a[0]), "r"(a[1]), "r"(a[2]), "r"(a[3]), "r"(b[0]), "r"(b[1]));
}
// tile rows are 128B (64 bf16); 16B-chunk index swizzled by row for
// conflict-free ldmatrix + cp.async
__device__ __forceinline__ uint32_t swz(uint32_t r, uint32_t c16) {
    return (r << 7) + ((c16 ^ (r & 7)) << 4);
}
__device__ __forceinline__ void split_hl(float v, __nv_bfloat16& h, __nv_bfloat16& l) {
    h = __float2bfloat16(v);
    l = __float2bfloat16(v - __bfloat162float(h));
}

// ---------------- kernel 0: weight transpose + hi/lo split -----------------
__global__ void wprep_kernel(const float* __restrict__ W,
                             __nv_bfloat16* __restrict__ oh,
                             __nv_bfloat16* __restrict__ ol, int K, int N) {
    int idx = blockIdx.x * 256 + threadIdx.x;
    if (idx >= K * N) return;
    int k = idx / N, n = idx % N;
    float v = W[idx];
    __nv_bfloat16 h, l; split_hl(v, h, l);
    oh[(size_t)n * K + k] = h;
    ol[(size_t)n * K + k] = l;
}

// ---------------- kernel 1: ss = silu(t_emb) @ time_w + time_b -------------
__global__ void time_mlp_kernel(const float* __restrict__ te,
                                const float* __restrict__ tw,
                                const float* __restrict__ tb) {
    __shared__ float st[TD];
    int b = blockIdx.y;
    for (int k = threadIdx.x; k < TD; k += blockDim.x) {
        float v = te[b * TD + k];
        st[k] = v / (1.f + __expf(-v));
    }
    __syncthreads();
    int j = blockIdx.x * blockDim.x + threadIdx.x;
    float acc = tb[j];
    for (int k = 0; k < TD; k++)
        acc = fmaf(st[k], tw[k * (2 * DIM) + j], acc);
    g_ss[b * 2 * DIM + j] = acc;
}

// ---------------- kernel 2: LayerNorm -> bf16 hi/lo ------------------------
template <int MOD>
__global__ void ln_kernel(const float* __restrict__ x,
                          const float* __restrict__ gam,
                          const float* __restrict__ bet,
                          __nv_bfloat16* __restrict__ oh,
                          __nv_bfloat16* __restrict__ ol) {
    int row  = blockIdx.x;
    int t    = threadIdx.x;
    int lane = t & 31, wid = t >> 5;
    float4 xv = ((const float4*)(x + (size_t)row * DIM))[t];
    float s  = xv.x + xv.y + xv.z + xv.w;
    float s2 = fmaf(xv.x, xv.x, fmaf(xv.y, xv.y, fmaf(xv.z, xv.z, xv.w * xv.w)));
    #pragma unroll
    for (int o = 16; o > 0; o >>= 1) {
        s  += __shfl_xor_sync(0xffffffffu, s,  o);
        s2 += __shfl_xor_sync(0xffffffffu, s2, o);
    }
    __shared__ float red[8];
    if (lane == 0) { red[wid] = s; red[4 + wid] = s2; }
    __syncthreads();
    s  = red[0] + red[1] + red[2] + red[3];
    s2 = red[4] + red[5] + red[6] + red[7];
    float mu   = s * (1.f / DIM);
    float var  = s2 * (1.f / DIM) - mu * mu;
    float rstd = rsqrtf(var + 1e-5f);

    float4 gg = ((const float4*)gam)[t];
    float4 bb = ((const float4*)bet)[t];
    float o4[4];
    o4[0] = (xv.x - mu) * rstd * gg.x + bb.x;
    o4[1] = (xv.y - mu) * rstd * gg.y + bb.y;
    o4[2] = (xv.z - mu) * rstd * gg.z + bb.z;
    o4[3] = (xv.w - mu) * rstd * gg.w + bb.w;
    if (MOD) {
        int b = row >> 13;
        float4 sc = ((const float4*)(g_ss + b * 2 * DIM))[t];
        float4 sh = ((const float4*)(g_ss + b * 2 * DIM + DIM))[t];
        o4[0] = o4[0] * (1.f + sc.x) + sh.x;
        o4[1] = o4[1] * (1.f + sc.y) + sh.y;
        o4[2] = o4[2] * (1.f + sc.z) + sh.z;
        o4[3] = o4[3] * (1.f + sc.w) + sh.w;
    }
    __nv_bfloat16 h[4], l[4];
    #pragma unroll
    for (int i = 0; i < 4; i++) split_hl(o4[i], h[i], l[i]);
    ((uint2*)(oh + (size_t)row * DIM))[t] =
        make_uint2(*(uint32_t*)&h[0] | ((uint32_t)*(uint16_t*)&h[1] << 16),
                   *(uint16_t*)&h[2] | ((uint32_t)*(uint16_t*)&h[3] << 16));
    ((uint2*)(ol + (size_t)row * DIM))[t] =
        make_uint2(*(uint16_t*)&l[0] | ((uint32_t)*(uint16_t*)&l[1] << 16),
                   *(uint16_t*)&l[2] | ((uint32_t)*(uint16_t*)&l[3] << 16));
}

// ---------------- kernel 3: mma.sync bf16 GEMM -----------------------------
// C[M,N] = A[M,K] @ B[N,K]^T (+bias, +res / gelu).
// A,B given as bf16 hi/lo pairs; 3-term split via 6 virtual k16 steps per
// 32 real K. Tile 128x128, 8 warps (64x32 each), 2-stage cp.async pipeline.
// EPI: 0 = bias -> f32 out; 1 = bias+res -> f32 out; 2 = bias+GELU -> hi/lo out
#define KSTEP 32
template <int EPI>
__global__ __launch_bounds__(256, 2)
void mma_gemm(const __nv_bfloat16* __restrict__ Ah,
              const __nv_bfloat16* __restrict__ Al,
              const __nv_bfloat16* __restrict__ Bh,
              const __nv_bfloat16* __restrict__ Bl,
              const float* __restrict__ bias,
              const float* __restrict__ res,
              float* __restrict__ Cf,
              __nv_bfloat16* __restrict__ Ch,
              __nv_bfloat16* __restrict__ Cl,
              int K, int N) {
    extern __shared__ char smem[];
    const uint32_t sbase = smem_u32(smem);
    const int tid = threadIdx.x, w = tid >> 5, lane = tid & 31;
    const int bm = blockIdx.y * 128, bn = blockIdx.x * 128;
    const int warpM = (w >> 2) * 64, warpN = (w & 3) * 32;
    const int T = K / KSTEP;

    // per-stage: A tile 128x64 bf16 (16KB: cols 0..31 = Ah, 32..63 = Al),
    //            B tile 128x64 bf16 (16KB: Bh | Bl)
    const int r_ld = tid >> 3, c_ld = tid & 7;   // 256 threads: 32 rows x 8 c16

    auto issue = [&](int t) {
        int k0 = t * KSTEP;
        uint32_t sa = sbase + (t & 1) * 32768;
        uint32_t sb = sa + 16384;
        #pragma unroll
        for (int i = 0; i < 4; i++) {
            int r = r_ld + i * 32;
            const __nv_bfloat16* srcA = (c_ld < 4)
                ? Ah + (size_t)(bm + r) * K + k0 + c_ld * 8
                : Al + (size_t)(bm + r) * K + k0 + (c_ld - 4) * 8;
            cp16(sa + swz(r, c_ld), srcA);
            const __nv_bfloat16* srcB = (c_ld < 4)
                ? Bh + (size_t)(bn + r) * K + k0 + c_ld * 8
                : Bl + (size_t)(bn + r) * K + k0 + (c_ld - 4) * 8;
            cp16(sb + swz(r, c_ld), srcB);
        }
        CP_COMMIT();
    };

    float acc[4][4][4];
    #pragma unroll
    for (int i = 0; i < 4; i++)
        #pragma unroll
        for (int j = 0; j < 4; j++)
            #pragma unroll
            for (int e = 0; e < 4; e++) acc[i][j][e] = 0.f;

    // ldmatrix lane address components
    const int laA_r = lane & 15, laA_h = lane >> 4;              // A: row, k-half
    const int laB_r = (lane & 7) + ((lane >> 4) << 3);           // B: n-row
    const int laB_h = (lane >> 3) & 1;                            // B: k-half

    issue(0);
    for (int t = 0; t < T; t++) {
        if (t + 1 < T) { issue(t + 1); CP_WAIT(1); }
        else           { CP_WAIT(0); }
        __syncthreads();

        uint32_t sa = sbase + (t & 1) * 32768;
        uint32_t sb = sa + 16384;
        // virtual k16 steps: (Ah,Bh)x2, (Ah,Bl)x2, (Al,Bh)x2
        const int SA[6] = {0, 1, 0, 1, 2, 3};
        const int SB[6] = {0, 1, 2, 3, 0, 1};
        #pragma unroll
        for (int s = 0; s < 6; s++) {
            int ka = SA[s], kb = SB[s];
            uint32_t afr[4][4], bfr[2][4];
            #pragma unroll
            for (int mi = 0; mi < 4; mi++) {
                uint32_t row = warpM + mi * 16 + laA_r;
                ldsm4(afr[mi], sa + swz(row, ka * 2 + laA_h));
            }
            #pragma unroll
            for (int nj = 0; nj < 2; nj++) {
                uint32_t row = warpN + nj * 16 + laB_r;
                ldsm4(bfr[nj], sb + swz(row, kb * 2 + laB_h));
            }
            #pragma unroll
            for (int mi = 0; mi < 4; mi++)
                #pragma unroll
                for (int n8 = 0; n8 < 4; n8++)
                    mma16816(acc[mi][n8], afr[mi], &bfr[n8 >> 1][(n8 & 1) * 2]);
        }
        __syncthreads();
    }

    // ----- epilogue: thread t owns rows t/4, t/4+8; cols (t%4)*2, +1 -------
    int tr = lane >> 2, tc = (lane & 3) * 2;
    #pragma unroll
    for (int mi = 0; mi < 4; mi++) {
        #pragma unroll
        for (int half = 0; half < 2; half++) {
            int row = bm + warpM + mi * 16 + tr + half * 8;
            size_t rowoff = (size_t)row * N;
            #pragma unroll
            for (int n8 = 0; n8 < 4; n8++) {
                int col = bn + warpN + n8 * 8 + tc;
                float2 bi = *(const float2*)(bias + col);
                float ox = acc[mi][n8][half * 2 + 0] + bi.x;
                float oy = acc[mi][n8][half * 2 + 1] + bi.y;
                if (EPI == 1) {
                    float2 rr = *(const float2*)(res + rowoff + col);
                    ox += rr.x; oy += rr.y;
                }
                if (EPI == 2) {
                    ox = 0.5f * ox * (1.f + erff(ox * 0.70710678118654752f));
                    oy = 0.5f * oy * (1.f + erff(oy * 0.70710678118654752f));
                    __nv_bfloat16 hx, lx, hy, ly;
                    split_hl(ox, hx, lx); split_hl(oy, hy, ly);
                    uint32_t ph = *(uint16_t*)&hx | ((uint32_t)*(uint16_t*)&hy << 16);
                    uint32_t pl = *(uint16_t*)&lx | ((uint32_t)*(uint16_t*)&ly << 16);
                    *(uint32_t*)(Ch + rowoff + col) = ph;
                    *(uint32_t*)(Cl + rowoff + col) = pl;
                } else {
                    *(float2*)(Cf + rowoff + col) = make_float2(ox, oy);
                }
            }
        }
    }
}

// ---------------- kernel 4: local windowed attention -----------------------
__global__ __launch_bounds__(128)
void attn_kernel(const float* __restrict__ qkv,
                 __nv_bfloat16* __restrict__ oh,
                 __nv_bfloat16* __restrict__ ol) {
    extern __shared__ float sm[];
    float* Ks = sm;                 // 128*64
    float* Vs = sm + 128 * 64;      // 128*64

    int w = blockIdx.x, h = blockIdx.y, b = blockIdx.z;
    int r = threadIdx.x;

    const float scale = 0.125f;
    int qtok = b * SEQ + w * WIN + r;
    const float* qptr = qkv + (size_t)qtok * (3 * DIM) + h * HD;

    float q[HD];
    #pragma unroll
    for (int d4 = 0; d4 < HD / 4; d4++) {
        float4 v4 = ((const float4*)qptr)[d4];
        q[4 * d4 + 0] = v4.x * scale;
        q[4 * d4 + 1] = v4.y * scale;
        q[4 * d4 + 2] = v4.z * scale;
        q[4 * d4 + 3] = v4.w * scale;
    }

    float acc[HD];
    #pragma unroll
    for (int d = 0; d < HD; d++) acc[d] = 0.f;
    float m = -1e30f, l = 0.f;

    #pragma unroll
    for (int dw = -1; dw <= 1; dw++) {
        int wi = w + dw;
        if (wi < 0 || wi >= NW) continue;
        __syncthreads();
        {
            int ktok = b * SEQ + wi * WIN + r;
            const float* kp = qkv + (size_t)ktok * (3 * DIM) + DIM     + h * HD;
            const float* vp = qkv + (size_t)ktok * (3 * DIM) + 2 * DIM + h * HD;
            #pragma unroll
            for (int d4 = 0; d4 < HD / 4; d4++) {
                ((float4*)(Ks + r * HD))[d4] = ((const float4*)kp)[d4];
                ((float4*)(Vs + r * HD))[d4] = ((const float4*)vp)[d4];
            }
        }
        __syncthreads();

        for (int jc = 0; jc < WIN; jc += 8) {
            float s8[8];
            #pragma unroll
            for (int jj = 0; jj < 8; jj++) {
                const float4* K4 = (const float4*)(Ks + (jc + jj) * HD);
                float s = 0.f;
                #pragma unroll
                for (int d4 = 0; d4 < HD / 4; d4++) {
                    float4 kv = K4[d4];
                    s = fmaf(q[4 * d4 + 0], kv.x, s);
                    s = fmaf(q[4 * d4 + 1], kv.y, s);
                    s = fmaf(q[4 * d4 + 2], kv.z, s);
                    s = fmaf(q[4 * d4 + 3], kv.w, s);
                }
                s8[jj] = s;
            }
            float cmax = s8[0];
            #pragma unroll
            for (int jj = 1; jj < 8; jj++) cmax = fmaxf(cmax, s8[jj]);
            float mnew = fmaxf(m, cmax);
            float corr = __expf(m - mnew);
            l *= corr;
            #pragma unroll
            for (int d = 0; d < HD; d++) acc[d] *= corr;
            #pragma unroll
            for (int jj = 0; jj < 8; jj++) {
                float p = __expf(s8[jj] - mnew);
                l += p;
                const float4* V4 = (const float4*)(Vs + (jc + jj) * HD);
                #pragma unroll
                for (int d4 = 0; d4 < HD / 4; d4++) {
                    float4 vv = V4[d4];
                    acc[4 * d4 + 0] = fmaf(p, vv.x, acc[4 * d4 + 0]);
                    acc[4 * d4 + 1] = fmaf(p, vv.y, acc[4 * d4 + 1]);
                    acc[4 * d4 + 2] = fmaf(p, vv.z, acc[4 * d4 + 2]);
                    acc[4 * d4 + 3] = fmaf(p, vv.w, acc[4 * d4 + 3]);
                }
            }
            m = mnew;
        }
    }

    float inv = 1.f / l;
    __nv_bfloat16* oph = oh + (size_t)qtok * DIM + h * HD;
    __nv_bfloat16* opl = ol + (size_t)qtok * DIM + h * HD;
    #pragma unroll
    for (int d2 = 0; d2 < HD / 2; d2++) {
        float vx = acc[2 * d2] * inv, vy = acc[2 * d2 + 1] * inv;
        __nv_bfloat16 hx, lx, hy, ly;
        split_hl(vx, hx, lx); split_hl(vy, hy, ly);
        *(uint32_t*)(oph + 2 * d2) =
            *(uint16_t*)&hx | ((uint32_t)*(uint16_t*)&hy << 16);
        *(uint32_t*)(opl + 2 * d2) =
            *(uint16_t*)&lx | ((uint32_t)*(uint16_t*)&ly << 16);
    }
}

// ---------------- kernel 5: final LN (fp32 out not needed; reuse ln) -------

// ---------------- host orchestration ---------------------------------------
extern "C" void kernel_launch(void* const* d_in, const int* in_sizes, int n_in,
                              void* d_out, int out_size) {
    const float* x      = (const float*)d_in[0];
    const float* t_emb  = (const float*)d_in[1];
    const float* ln1_g  = (const float*)d_in[2];
    const float* ln1_b  = (const float*)d_in[3];
    const float* qkv_w  = (const float*)d_in[4];
    const float* qkv_b  = (const float*)d_in[5];
    const float* proj_w = (const float*)d_in[6];
    const float* proj_b = (const float*)d_in[7];
    const float* ln2_g  = (const float*)d_in[8];
    const float* ln2_b  = (const float*)d_in[9];
    const float* mlp_w1 = (const float*)d_in[10];
    const float* mlp_b1 = (const float*)d_in[11];
    const float* mlp_w2 = (const float*)d_in[12];
    const float* mlp_b2 = (const float*)d_in[13];
    const float* time_w = (const float*)d_in[14];
    const float* time_b = (const float*)d_in[15];
    float* out = (float*)d_out;

    void* p;
    float *qkv, *y;
    __nv_bfloat16 *xh, *xl, *ah, *al, *fh, *fl;
    __nv_bfloat16 *wq_h, *wq_l, *wp_h, *wp_l, *w1_h, *w1_l, *w2_h, *w2_l;
    cudaGetSymbolAddress(&p, g_qkv);  qkv = (float*)p;
    cudaGetSymbolAddress(&p, g_y);    y   = (float*)p;
    cudaGetSymbolAddress(&p, g_xh);   xh  = (__nv_bfloat16*)p;
    cudaGetSymbolAddress(&p, g_xl);   xl  = (__nv_bfloat16*)p;
    cudaGetSymbolAddress(&p, g_ah);   ah  = (__nv_bfloat16*)p;
    cudaGetSymbolAddress(&p, g_al);   al  = (__nv_bfloat16*)p;
    cudaGetSymbolAddress(&p, g_fh);   fh  = (__nv_bfloat16*)p;
    cudaGetSymbolAddress(&p, g_fl);   fl  = (__nv_bfloat16*)p;
    cudaGetSymbolAddress(&p, g_wq_h); wq_h = (__nv_bfloat16*)p;
    cudaGetSymbolAddress(&p, g_wq_l); wq_l = (__nv_bfloat16*)p;
    cudaGetSymbolAddress(&p, g_wp_h); wp_h = (__nv_bfloat16*)p;
    cudaGetSymbolAddress(&p, g_wp_l); wp_l = (__nv_bfloat16*)p;
    cudaGetSymbolAddress(&p, g_w1_h); w1_h = (__nv_bfloat16*)p;
    cudaGetSymbolAddress(&p, g_w1_l); w1_l = (__nv_bfloat16*)p;
    cudaGetSymbolAddress(&p, g_w2_h); w2_h = (__nv_bfloat16*)p;
    cudaGetSymbolAddress(&p, g_w2_l); w2_l = (__nv_bfloat16*)p;

    const int gemm_smem = 65536;
    cudaFuncSetAttribute(mma_gemm<0>, cudaFuncAttributeMaxDynamicSharedMemorySize, gemm_smem);
    cudaFuncSetAttribute(mma_gemm<1>, cudaFuncAttributeMaxDynamicSharedMemorySize, gemm_smem);
    cudaFuncSetAttribute(mma_gemm<2>, cudaFuncAttributeMaxDynamicSharedMemorySize, gemm_smem);
    const int attn_smem = 2 * 128 * 64 * sizeof(float);   // 64 KB
    cudaFuncSetAttribute(attn_kernel, cudaFuncAttributeMaxDynamicSharedMemorySize, attn_smem);

    // 0. weight prep (transpose + hi/lo split)
    wprep_kernel<<<(512 * 1536 + 255) / 256, 256>>>(qkv_w,  wq_h, wq_l, 512, 1536);
    wprep_kernel<<<(512 * 512  + 255) / 256, 256>>>(proj_w, wp_h, wp_l, 512, 512);
    wprep_kernel<<<(512 * 2048 + 255) / 256, 256>>>(mlp_w1, w1_h, w1_l, 512, 2048);
    wprep_kernel<<<(2048 * 512 + 255) / 256, 256>>>(mlp_w2, w2_h, w2_l, 2048, 512);
    // 1. adaLN scale/shift
    time_mlp_kernel<<<dim3(2 * DIM / 256, B_), 256>>>(t_emb, time_w, time_b);
    // 2. modulated LN1 -> bf16 hi/lo
    ln_kernel<1><<<NTOK, 128>>>(x, ln1_g, ln1_b, xh, xl);
    // 3. QKV GEMM -> fp32 qkv
    mma_gemm<0><<<dim3(12, NTOK / 128), 256, gemm_smem>>>(
        xh, xl, wq_h, wq_l, qkv_b, nullptr, qkv, nullptr, nullptr, 512, 1536);
    // 4. local attention -> bf16 hi/lo
    attn_kernel<<<dim3(NW, HEADS, B_), 128, attn_smem>>>(qkv, ah, al);
    // 5. proj + residual(x) -> fp32 y
    mma_gemm<1><<<dim3(4, NTOK / 128), 256, gemm_smem>>>(
        ah, al, wp_h, wp_l, proj_b, x, y, nullptr, nullptr, 512, 512);
    // 6. LN2 -> bf16 hi/lo
    ln_kernel<0><<<NTOK, 128>>>(y, ln2_g, ln2_b, xh, xl);
    // 7. MLP up + GELU -> bf16 hi/lo
    mma_gemm<2><<<dim3(16, NTOK / 128), 256, gemm_smem>>>(
        xh, xl, w1_h, w1_l, mlp_b1, nullptr, nullptr, fh, fl, 512, 2048);
    // 8. MLP down + residual(y) -> out
    mma_gemm<1><<<dim3(4, NTOK / 128), 256, gemm_smem>>>(
        fh, fl, w2_h, w2_l, mlp_b2, y, out, nullptr, nullptr, 2048, 512);
}

// round 5
// speedup vs baseline: 2.8143x; 1.3658x over previous
#include <cuda_runtime.h>
#include <cuda_bf16.h>
#include <math.h>
#include <cstdint>

#define B_    8
#define SEQ   8192
#define DIM   512
#define HEADS 8
#define HD    64
#define FF_   2048
#define WIN   128
#define TD    512
#define NTOK  (B_*SEQ)        // 65536
#define NW    (SEQ/WIN)       // 64

// ---------------- scratch (device globals; no runtime allocation) ----------
__device__ float g_ss  [B_ * 2 * DIM];
__device__ float g_qkv [(size_t)NTOK * 3 * DIM];   // fp32 qkv
__device__ float g_y   [(size_t)NTOK * DIM];       // x + proj(attn), fp32
// hi/lo bf16 activations (GEMM A operands)
__device__ __nv_bfloat16 g_xh [(size_t)NTOK * DIM],  g_xl [(size_t)NTOK * DIM];
__device__ __nv_bfloat16 g_ah [(size_t)NTOK * DIM],  g_al [(size_t)NTOK * DIM];
__device__ __nv_bfloat16 g_fh [(size_t)NTOK * FF_],  g_fl [(size_t)NTOK * FF_];
// weights hi/lo, transposed to [N][K] bf16 (K contiguous)
__device__ __nv_bfloat16 g_wq_h[1536 * 512],  g_wq_l[1536 * 512];
__device__ __nv_bfloat16 g_wp_h[512 * 512],   g_wp_l[512 * 512];
__device__ __nv_bfloat16 g_w1_h[2048 * 512],  g_w1_l[2048 * 512];
__device__ __nv_bfloat16 g_w2_h[512 * 2048],  g_w2_l[512 * 2048];

// ---------------- PTX helpers ----------------------------------------------
__device__ __forceinline__ uint32_t smem_u32(const void* p) {
    uint32_t a;
    asm("{ .reg .u64 t; cvta.to.shared.u64 t, %1; cvt.u32.u64 %0, t; }"
        : "=r"(a) : "l"(p));
    return a;
}
__device__ __forceinline__ void cp16(uint32_t dst, const void* src) {
    asm volatile("cp.async.cg.shared.global [%0], [%1], 16;"
                 :: "r"(dst), "l"(src) : "memory");
}
#define CP_COMMIT() asm volatile("cp.async.commit_group;" ::: "memory")
#define CP_WAIT(n)  asm volatile("cp.async.wait_group %0;" :: "n"(n) : "memory")

__device__ __forceinline__ void ldsm4(uint32_t* r, uint32_t addr) {
    asm volatile("ldmatrix.sync.aligned.m8n8.x4.shared.b16 {%0,%1,%2,%3}, [%4];"
                 : "=r"(r[0]), "=r"(r[1]), "=r"(r[2]), "=r"(r[3]) : "r"(addr));
}
__device__ __forceinline__ void ldsm4t(uint32_t* r, uint32_t addr) {
    asm volatile("ldmatrix.sync.aligned.m8n8.x4.trans.shared.b16 {%0,%1,%2,%3}, [%4];"
                 : "=r"(r[0]), "=r"(r[1]), "=r"(r[2]), "=r"(r[3]) : "r"(addr));
}
__device__ __forceinline__ void mma16816(float* d, const uint32_t* a,
                                         const uint32_t* b) {
    asm volatile(
        "mma.sync.aligned.m16n8k16.row.col.f32.bf16.bf16.f32 "
        "{%0,%1,%2,%3}, {%4,%5,%6,%7}, {%8,%9}, {%0,%1,%2,%3};"
        : "+f"(d[0]), "+f"(d[1]), "+f"(d[2]), "+f"(d[3])
        : "r"(a[0]), "r"(a[1]), "r"(a[2]), "r"(a[3]), "r"(b[0]), "r"(b[1]));
}
// tile rows are 128B (64 bf16); 16B-chunk index swizzled by row
__device__ __forceinline__ uint32_t swz(uint32_t r, uint32_t c16) {
    return (r << 7) + ((c16 ^ (r & 7)) << 4);
}
__device__ __forceinline__ void split_hl(float v, __nv_bfloat16& h, __nv_bfloat16& l) {
    h = __float2bfloat16(v);
    l = __float2bfloat16(v - __bfloat162float(h));
}
__device__ __forceinline__ uint32_t pack_bf2(__nv_bfloat16 a, __nv_bfloat16 b) {
    __nv_bfloat162 p = __halves2bfloat162(a, b);
    return *reinterpret_cast<uint32_t*>(&p);
}

// ---------------- kernel 0: coalesced weight transpose + hi/lo split -------
__global__ void wprep_kernel(const float* __restrict__ W,
                             __nv_bfloat16* __restrict__ oh,
                             __nv_bfloat16* __restrict__ ol, int K, int N) {
    __shared__ float tile[32][33];
    int bx = blockIdx.x * 32, by = blockIdx.y * 32;
    int tx = threadIdx.x, ty = threadIdx.y;
    #pragma unroll
    for (int i = 0; i < 4; i++) {
        int k = by + ty + i * 8;
        tile[ty + i * 8][tx] = W[(size_t)k * N + bx + tx];
    }
    __syncthreads();
    #pragma unroll
    for (int i = 0; i < 4; i++) {
        int n = bx + ty + i * 8;
        int k = by + tx;
        float v = tile[tx][ty + i * 8];
        __nv_bfloat16 h, l; split_hl(v, h, l);
        oh[(size_t)n * K + k] = h;
        ol[(size_t)n * K + k] = l;
    }
}

// ---------------- kernel 1: ss = silu(t_emb) @ time_w + time_b -------------
__global__ void time_mlp_kernel(const float* __restrict__ te,
                                const float* __restrict__ tw,
                                const float* __restrict__ tb) {
    __shared__ float st[TD];
    int b = blockIdx.y;
    for (int k = threadIdx.x; k < TD; k += blockDim.x) {
        float v = te[b * TD + k];
        st[k] = v / (1.f + __expf(-v));
    }
    __syncthreads();
    int j = blockIdx.x * blockDim.x + threadIdx.x;
    float acc = tb[j];
    for (int k = 0; k < TD; k++)
        acc = fmaf(st[k], tw[k * (2 * DIM) + j], acc);
    g_ss[b * 2 * DIM + j] = acc;
}

// ---------------- kernel 2: LayerNorm -> bf16 hi/lo ------------------------
template <int MOD>
__global__ void ln_kernel(const float* __restrict__ x,
                          const float* __restrict__ gam,
                          const float* __restrict__ bet,
                          __nv_bfloat16* __restrict__ oh,
                          __nv_bfloat16* __restrict__ ol) {
    int row  = blockIdx.x;
    int t    = threadIdx.x;
    int lane = t & 31, wid = t >> 5;
    float4 xv = ((const float4*)(x + (size_t)row * DIM))[t];
    float s  = xv.x + xv.y + xv.z + xv.w;
    float s2 = fmaf(xv.x, xv.x, fmaf(xv.y, xv.y, fmaf(xv.z, xv.z, xv.w * xv.w)));
    #pragma unroll
    for (int o = 16; o > 0; o >>= 1) {
        s  += __shfl_xor_sync(0xffffffffu, s,  o);
        s2 += __shfl_xor_sync(0xffffffffu, s2, o);
    }
    __shared__ float red[8];
    if (lane == 0) { red[wid] = s; red[4 + wid] = s2; }
    __syncthreads();
    s  = red[0] + red[1] + red[2] + red[3];
    s2 = red[4] + red[5] + red[6] + red[7];
    float mu   = s * (1.f / DIM);
    float var  = s2 * (1.f / DIM) - mu * mu;
    float rstd = rsqrtf(var + 1e-5f);

    float4 gg = ((const float4*)gam)[t];
    float4 bb = ((const float4*)bet)[t];
    float o4[4];
    o4[0] = (xv.x - mu) * rstd * gg.x + bb.x;
    o4[1] = (xv.y - mu) * rstd * gg.y + bb.y;
    o4[2] = (xv.z - mu) * rstd * gg.z + bb.z;
    o4[3] = (xv.w - mu) * rstd * gg.w + bb.w;
    if (MOD) {
        int b = row >> 13;
        float4 sc = ((const float4*)(g_ss + b * 2 * DIM))[t];
        float4 sh = ((const float4*)(g_ss + b * 2 * DIM + DIM))[t];
        o4[0] = o4[0] * (1.f + sc.x) + sh.x;
        o4[1] = o4[1] * (1.f + sc.y) + sh.y;
        o4[2] = o4[2] * (1.f + sc.z) + sh.z;
        o4[3] = o4[3] * (1.f + sc.w) + sh.w;
    }
    __nv_bfloat16 h[4], l[4];
    #pragma unroll
    for (int i = 0; i < 4; i++) split_hl(o4[i], h[i], l[i]);
    ((uint2*)(oh + (size_t)row * DIM))[t] =
        make_uint2(pack_bf2(h[0], h[1]), pack_bf2(h[2], h[3]));
    ((uint2*)(ol + (size_t)row * DIM))[t] =
        make_uint2(pack_bf2(l[0], l[1]), pack_bf2(l[2], l[3]));
}

// ---------------- kernel 3: mma.sync bf16 GEMM -----------------------------
#define KSTEP 32
template <int EPI>
__global__ __launch_bounds__(256, 2)
void mma_gemm(const __nv_bfloat16* __restrict__ Ah,
              const __nv_bfloat16* __restrict__ Al,
              const __nv_bfloat16* __restrict__ Bh,
              const __nv_bfloat16* __restrict__ Bl,
              const float* __restrict__ bias,
              const float* __restrict__ res,
              float* __restrict__ Cf,
              __nv_bfloat16* __restrict__ Ch,
              __nv_bfloat16* __restrict__ Cl,
              int K, int N) {
    extern __shared__ char smem[];
    const uint32_t sbase = smem_u32(smem);
    const int tid = threadIdx.x, w = tid >> 5, lane = tid & 31;
    const int bm = blockIdx.y * 128, bn = blockIdx.x * 128;
    const int warpM = (w >> 2) * 64, warpN = (w & 3) * 32;
    const int T = K / KSTEP;

    const int r_ld = tid >> 3, c_ld = tid & 7;

    auto issue = [&](int t) {
        int k0 = t * KSTEP;
        uint32_t sa = sbase + (t & 1) * 32768;
        uint32_t sb = sa + 16384;
        #pragma unroll
        for (int i = 0; i < 4; i++) {
            int r = r_ld + i * 32;
            const __nv_bfloat16* srcA = (c_ld < 4)
                ? Ah + (size_t)(bm + r) * K + k0 + c_ld * 8
                : Al + (size_t)(bm + r) * K + k0 + (c_ld - 4) * 8;
            cp16(sa + swz(r, c_ld), srcA);
            const __nv_bfloat16* srcB = (c_ld < 4)
                ? Bh + (size_t)(bn + r) * K + k0 + c_ld * 8
                : Bl + (size_t)(bn + r) * K + k0 + (c_ld - 4) * 8;
            cp16(sb + swz(r, c_ld), srcB);
        }
        CP_COMMIT();
    };

    float acc[4][4][4];
    #pragma unroll
    for (int i = 0; i < 4; i++)
        #pragma unroll
        for (int j = 0; j < 4; j++)
            #pragma unroll
            for (int e = 0; e < 4; e++) acc[i][j][e] = 0.f;

    const int laA_r = lane & 15, laA_h = lane >> 4;
    const int laB_r = (lane & 7) + ((lane >> 4) << 3);
    const int laB_h = (lane >> 3) & 1;

    issue(0);
    for (int t = 0; t < T; t++) {
        if (t + 1 < T) { issue(t + 1); CP_WAIT(1); }
        else           { CP_WAIT(0); }
        __syncthreads();

        uint32_t sa = sbase + (t & 1) * 32768;
        uint32_t sb = sa + 16384;
        const int SA[6] = {0, 1, 0, 1, 2, 3};
        const int SB[6] = {0, 1, 2, 3, 0, 1};
        #pragma unroll
        for (int s = 0; s < 6; s++) {
            int ka = SA[s], kb = SB[s];
            uint32_t afr[4][4], bfr[2][4];
            #pragma unroll
            for (int mi = 0; mi < 4; mi++) {
                uint32_t row = warpM + mi * 16 + laA_r;
                ldsm4(afr[mi], sa + swz(row, ka * 2 + laA_h));
            }
            #pragma unroll
            for (int nj = 0; nj < 2; nj++) {
                uint32_t row = warpN + nj * 16 + laB_r;
                ldsm4(bfr[nj], sb + swz(row, kb * 2 + laB_h));
            }
            #pragma unroll
            for (int mi = 0; mi < 4; mi++)
                #pragma unroll
                for (int n8 = 0; n8 < 4; n8++)
                    mma16816(acc[mi][n8], afr[mi], &bfr[n8 >> 1][(n8 & 1) * 2]);
        }
        __syncthreads();
    }

    int tr = lane >> 2, tc = (lane & 3) * 2;
    #pragma unroll
    for (int mi = 0; mi < 4; mi++) {
        #pragma unroll
        for (int half = 0; half < 2; half++) {
            int row = bm + warpM + mi * 16 + tr + half * 8;
            size_t rowoff = (size_t)row * N;
            #pragma unroll
            for (int n8 = 0; n8 < 4; n8++) {
                int col = bn + warpN + n8 * 8 + tc;
                float2 bi = *(const float2*)(bias + col);
                float ox = acc[mi][n8][half * 2 + 0] + bi.x;
                float oy = acc[mi][n8][half * 2 + 1] + bi.y;
                if (EPI == 1) {
                    float2 rr = *(const float2*)(res + rowoff + col);
                    ox += rr.x; oy += rr.y;
                }
                if (EPI == 2) {
                    ox = 0.5f * ox * (1.f + erff(ox * 0.70710678118654752f));
                    oy = 0.5f * oy * (1.f + erff(oy * 0.70710678118654752f));
                    __nv_bfloat16 hx, lx, hy, ly;
                    split_hl(ox, hx, lx); split_hl(oy, hy, ly);
                    *(uint32_t*)(Ch + rowoff + col) = pack_bf2(hx, hy);
                    *(uint32_t*)(Cl + rowoff + col) = pack_bf2(lx, ly);
                } else {
                    *(float2*)(Cf + rowoff + col) = make_float2(ox, oy);
                }
            }
        }
    }
}

// ---------------- kernel 4: local windowed attention via mma.sync ----------
// grid (NW, HEADS, B_), 128 threads (4 warps x 32 query rows).
// Flash-style: S = Q@K^T (3-term bf16 split), online softmax in regs,
// O += P@V (3-term: PhVh + PhVl + PlVh; P-frag from acc-layout pack,
// V-frag via ldmatrix.trans). smem: Q/K/V hi+lo tiles (96 KB).
__global__ __launch_bounds__(128)
void attn_mma_kernel(const float* __restrict__ qkv,
                     __nv_bfloat16* __restrict__ oh,
                     __nv_bfloat16* __restrict__ ol) {
    extern __shared__ char smc[];
    const uint32_t sQh = smem_u32(smc);
    const uint32_t sQl = sQh + 16384;
    const uint32_t sKh = sQh + 32768;
    const uint32_t sKl = sQh + 49152;
    const uint32_t sVh = sQh + 65536;
    const uint32_t sVl = sQh + 81920;

    const int w = blockIdx.x, h = blockIdx.y, b = blockIdx.z;
    const int tid = threadIdx.x, lane = tid & 31;
    const int warpM = (tid >> 5) * 32;

    const int laA_r = lane & 15, laA_h = lane >> 4;
    const int laB_r = (lane & 7) + ((lane >> 4) << 3);
    const int laB_h = (lane >> 3) & 1;

    // ---- load Q (x 0.125) -> hi/lo smem (thread = query row) ----
    {
        const float* qp = qkv + (size_t)(b * SEQ + w * WIN + tid) * (3 * DIM) + h * HD;
        #pragma unroll
        for (int c = 0; c < 8; c++) {
            float4 v0 = ((const float4*)qp)[c * 2];
            float4 v1 = ((const float4*)qp)[c * 2 + 1];
            float f[8] = {v0.x, v0.y, v0.z, v0.w, v1.x, v1.y, v1.z, v1.w};
            uint32_t hp[4], lp[4];
            #pragma unroll
            for (int e = 0; e < 4; e++) {
                __nv_bfloat16 h0, l0, h1, l1;
                split_hl(f[2 * e] * 0.125f, h0, l0);
                split_hl(f[2 * e + 1] * 0.125f, h1, l1);
                hp[e] = pack_bf2(h0, h1);
                lp[e] = pack_bf2(l0, l1);
            }
            uint32_t off = swz((uint32_t)tid, (uint32_t)c);
            *(uint4*)(smc + off)         = make_uint4(hp[0], hp[1], hp[2], hp[3]);
            *(uint4*)(smc + 16384 + off) = make_uint4(lp[0], lp[1], lp[2], lp[3]);
        }
    }

    float O[2][8][4];
    #pragma unroll
    for (int mt = 0; mt < 2; mt++)
        #pragma unroll
        for (int n8 = 0; n8 < 8; n8++)
            #pragma unroll
            for (int e = 0; e < 4; e++) O[mt][n8][e] = 0.f;
    float mS[2][2] = {{-1e30f, -1e30f}, {-1e30f, -1e30f}};
    float lS[2][2] = {{0.f, 0.f}, {0.f, 0.f}};

    for (int dw = -1; dw <= 1; dw++) {
        int wi = w + dw;
        if (wi < 0 || wi >= NW) continue;
        __syncthreads();
        // ---- load K,V window -> hi/lo smem (thread = key row) ----
        {
            const float* kp = qkv + (size_t)(b * SEQ + wi * WIN + tid) * (3 * DIM) + DIM + h * HD;
            const float* vp = kp + DIM;
            #pragma unroll
            for (int c = 0; c < 8; c++) {
                float4 k0 = ((const float4*)kp)[c * 2];
                float4 k1 = ((const float4*)kp)[c * 2 + 1];
                float4 u0 = ((const float4*)vp)[c * 2];
                float4 u1 = ((const float4*)vp)[c * 2 + 1];
                float fk[8] = {k0.x, k0.y, k0.z, k0.w, k1.x, k1.y, k1.z, k1.w};
                float fv[8] = {u0.x, u0.y, u0.z, u0.w, u1.x, u1.y, u1.z, u1.w};
                uint32_t kh[4], kl[4], vh[4], vl[4];
                #pragma unroll
                for (int e = 0; e < 4; e++) {
                    __nv_bfloat16 a0, b0, a1, b1;
                    split_hl(fk[2 * e], a0, b0); split_hl(fk[2 * e + 1], a1, b1);
                    kh[e] = pack_bf2(a0, a1); kl[e] = pack_bf2(b0, b1);
                    split_hl(fv[2 * e], a0, b0); split_hl(fv[2 * e + 1], a1, b1);
                    vh[e] = pack_bf2(a0, a1); vl[e] = pack_bf2(b0, b1);
                }
                uint32_t off = swz((uint32_t)tid, (uint32_t)c);
                *(uint4*)(smc + 32768 + off) = make_uint4(kh[0], kh[1], kh[2], kh[3]);
                *(uint4*)(smc + 49152 + off) = make_uint4(kl[0], kl[1], kl[2], kl[3]);
                *(uint4*)(smc + 65536 + off) = make_uint4(vh[0], vh[1], vh[2], vh[3]);
                *(uint4*)(smc + 81920 + off) = make_uint4(vl[0], vl[1], vl[2], vl[3]);
            }
        }
        __syncthreads();

        #pragma unroll
        for (int c0 = 0; c0 < 128; c0 += 64) {
            // ---- S = Q @ K^T for 64-key chunk (3-term split) ----
            float S[2][8][4];
            #pragma unroll
            for (int mt = 0; mt < 2; mt++)
                #pragma unroll
                for (int n8 = 0; n8 < 8; n8++)
                    #pragma unroll
                    for (int e = 0; e < 4; e++) S[mt][n8][e] = 0.f;

            #pragma unroll
            for (int kb = 0; kb < 4; kb++) {
                uint32_t aqh[2][4], aql[2][4], bkh[4][4], bkl[4][4];
                #pragma unroll
                for (int mt = 0; mt < 2; mt++) {
                    uint32_t row = warpM + mt * 16 + laA_r;
                    ldsm4(aqh[mt], sQh + swz(row, kb * 2 + laA_h));
                    ldsm4(aql[mt], sQl + swz(row, kb * 2 + laA_h));
                }
                #pragma unroll
                for (int np = 0; np < 4; np++) {
                    uint32_t row = c0 + np * 16 + laB_r;
                    ldsm4(bkh[np], sKh + swz(row, kb * 2 + laB_h));
                    ldsm4(bkl[np], sKl + swz(row, kb * 2 + laB_h));
                }
                #pragma unroll
                for (int mt = 0; mt < 2; mt++)
                    #pragma unroll
                    for (int n8 = 0; n8 < 8; n8++) {
                        const uint32_t* bh2 = &bkh[n8 >> 1][(n8 & 1) * 2];
                        const uint32_t* bl2 = &bkl[n8 >> 1][(n8 & 1) * 2];
                        mma16816(S[mt][n8], aqh[mt], bh2);
                        mma16816(S[mt][n8], aqh[mt], bl2);
                        mma16816(S[mt][n8], aql[mt], bh2);
                    }
            }

            // ---- online softmax on S (rows: lane/4 (+8); row group = 4 lanes) ----
            #pragma unroll
            for (int mt = 0; mt < 2; mt++) {
                #pragma unroll
                for (int half = 0; half < 2; half++) {
                    float cm = -1e30f;
                    #pragma unroll
                    for (int n8 = 0; n8 < 8; n8++) {
                        cm = fmaxf(cm, S[mt][n8][half * 2 + 0]);
                        cm = fmaxf(cm, S[mt][n8][half * 2 + 1]);
                    }
                    cm = fmaxf(cm, __shfl_xor_sync(0xffffffffu, cm, 1));
                    cm = fmaxf(cm, __shfl_xor_sync(0xffffffffu, cm, 2));
                    float mn = fmaxf(mS[mt][half], cm);
                    float corr = __expf(mS[mt][half] - mn);
                    float rs = 0.f;
                    #pragma unroll
                    for (int n8 = 0; n8 < 8; n8++) {
                        float p0 = __expf(S[mt][n8][half * 2 + 0] - mn);
                        float p1 = __expf(S[mt][n8][half * 2 + 1] - mn);
                        S[mt][n8][half * 2 + 0] = p0;
                        S[mt][n8][half * 2 + 1] = p1;
                        rs += p0 + p1;
                    }
                    rs += __shfl_xor_sync(0xffffffffu, rs, 1);
                    rs += __shfl_xor_sync(0xffffffffu, rs, 2);
                    lS[mt][half] = lS[mt][half] * corr + rs;
                    mS[mt][half] = mn;
                    #pragma unroll
                    for (int n8 = 0; n8 < 8; n8++) {
                        O[mt][n8][half * 2 + 0] *= corr;
                        O[mt][n8][half * 2 + 1] *= corr;
                    }
                }
            }

            // ---- O += P @ V (3-term: PhVh + PhVl + PlVh) ----
            #pragma unroll
            for (int kb = 0; kb < 4; kb++) {
                uint32_t ph[2][4], pl[2][4];
                #pragma unroll
                for (int mt = 0; mt < 2; mt++) {
                    #pragma unroll
                    for (int i = 0; i < 4; i++) {
                        int j = 2 * kb + (i >> 1);
                        float p0 = S[mt][j][(i & 1) * 2 + 0];
                        float p1 = S[mt][j][(i & 1) * 2 + 1];
                        __nv_bfloat16 h0 = __float2bfloat16(p0);
                        __nv_bfloat16 h1 = __float2bfloat16(p1);
                        ph[mt][i] = pack_bf2(h0, h1);
                        pl[mt][i] = pack_bf2(
                            __float2bfloat16(p0 - __bfloat162float(h0)),
                            __float2bfloat16(p1 - __bfloat162float(h1)));
                    }
                }
                uint32_t vfh[4][4], vfl[4][4];
                #pragma unroll
                for (int np = 0; np < 4; np++) {
                    uint32_t row = c0 + kb * 16 + (lane & 15);
                    uint32_t ch = np * 2 + (lane >> 4);
                    ldsm4t(vfh[np], sVh + swz(row, ch));
                    ldsm4t(vfl[np], sVl + swz(row, ch));
                }
                #pragma unroll
                for (int mt = 0; mt < 2; mt++)
                    #pragma unroll
                    for (int n8 = 0; n8 < 8; n8++) {
                        const uint32_t* vh2 = &vfh[n8 >> 1][(n8 & 1) * 2];
                        const uint32_t* vl2 = &vfl[n8 >> 1][(n8 & 1) * 2];
                        mma16816(O[mt][n8], ph[mt], vh2);
                        mma16816(O[mt][n8], ph[mt], vl2);
                        mma16816(O[mt][n8], pl[mt], vh2);
                    }
            }
        }
    }

    // ---- epilogue: normalize, split hi/lo, store ----
    #pragma unroll
    for (int mt = 0; mt < 2; mt++) {
        #pragma unroll
        for (int half = 0; half < 2; half++) {
            float inv = 1.f / lS[mt][half];
            int row = warpM + mt * 16 + (lane >> 2) + half * 8;
            size_t base = (size_t)(b * SEQ + w * WIN + row) * DIM + h * HD;
            #pragma unroll
            for (int n8 = 0; n8 < 8; n8++) {
                int col = n8 * 8 + (lane & 3) * 2;
                float x0 = O[mt][n8][half * 2 + 0] * inv;
                float x1 = O[mt][n8][half * 2 + 1] * inv;
                __nv_bfloat16 h0, l0, h1, l1;
                split_hl(x0, h0, l0); split_hl(x1, h1, l1);
                *(uint32_t*)(oh + base + col) = pack_bf2(h0, h1);
                *(uint32_t*)(ol + base + col) = pack_bf2(l0, l1);
            }
        }
    }
}

// ---------------- host orchestration ---------------------------------------
extern "C" void kernel_launch(void* const* d_in, const int* in_sizes, int n_in,
                              void* d_out, int out_size) {
    const float* x      = (const float*)d_in[0];
    const float* t_emb  = (const float*)d_in[1];
    const float* ln1_g  = (const float*)d_in[2];
    const float* ln1_b  = (const float*)d_in[3];
    const float* qkv_w  = (const float*)d_in[4];
    const float* qkv_b  = (const float*)d_in[5];
    const float* proj_w = (const float*)d_in[6];
    const float* proj_b = (const float*)d_in[7];
    const float* ln2_g  = (const float*)d_in[8];
    const float* ln2_b  = (const float*)d_in[9];
    const float* mlp_w1 = (const float*)d_in[10];
    const float* mlp_b1 = (const float*)d_in[11];
    const float* mlp_w2 = (const float*)d_in[12];
    const float* mlp_b2 = (const float*)d_in[13];
    const float* time_w = (const float*)d_in[14];
    const float* time_b = (const float*)d_in[15];
    float* out = (float*)d_out;

    void* p;
    float *qkv, *y;
    __nv_bfloat16 *xh, *xl, *ah, *al, *fh, *fl;
    __nv_bfloat16 *wq_h, *wq_l, *wp_h, *wp_l, *w1_h, *w1_l, *w2_h, *w2_l;
    cudaGetSymbolAddress(&p, g_qkv);  qkv = (float*)p;
    cudaGetSymbolAddress(&p, g_y);    y   = (float*)p;
    cudaGetSymbolAddress(&p, g_xh);   xh  = (__nv_bfloat16*)p;
    cudaGetSymbolAddress(&p, g_xl);   xl  = (__nv_bfloat16*)p;
    cudaGetSymbolAddress(&p, g_ah);   ah  = (__nv_bfloat16*)p;
    cudaGetSymbolAddress(&p, g_al);   al  = (__nv_bfloat16*)p;
    cudaGetSymbolAddress(&p, g_fh);   fh  = (__nv_bfloat16*)p;
    cudaGetSymbolAddress(&p, g_fl);   fl  = (__nv_bfloat16*)p;
    cudaGetSymbolAddress(&p, g_wq_h); wq_h = (__nv_bfloat16*)p;
    cudaGetSymbolAddress(&p, g_wq_l); wq_l = (__nv_bfloat16*)p;
    cudaGetSymbolAddress(&p, g_wp_h); wp_h = (__nv_bfloat16*)p;
    cudaGetSymbolAddress(&p, g_wp_l); wp_l = (__nv_bfloat16*)p;
    cudaGetSymbolAddress(&p, g_w1_h); w1_h = (__nv_bfloat16*)p;
    cudaGetSymbolAddress(&p, g_w1_l); w1_l = (__nv_bfloat16*)p;
    cudaGetSymbolAddress(&p, g_w2_h); w2_h = (__nv_bfloat16*)p;
    cudaGetSymbolAddress(&p, g_w2_l); w2_l = (__nv_bfloat16*)p;

    const int gemm_smem = 65536;
    cudaFuncSetAttribute(mma_gemm<0>, cudaFuncAttributeMaxDynamicSharedMemorySize, gemm_smem);
    cudaFuncSetAttribute(mma_gemm<1>, cudaFuncAttributeMaxDynamicSharedMemorySize, gemm_smem);
    cudaFuncSetAttribute(mma_gemm<2>, cudaFuncAttributeMaxDynamicSharedMemorySize, gemm_smem);
    const int attn_smem = 98304;    // Q/K/V hi+lo, 16KB each
    cudaFuncSetAttribute(attn_mma_kernel, cudaFuncAttributeMaxDynamicSharedMemorySize, attn_smem);

    // 0. weight prep (coalesced transpose + hi/lo split)
    wprep_kernel<<<dim3(1536 / 32, 512 / 32), dim3(32, 8)>>>(qkv_w,  wq_h, wq_l, 512, 1536);
    wprep_kernel<<<dim3(512 / 32,  512 / 32), dim3(32, 8)>>>(proj_w, wp_h, wp_l, 512, 512);
    wprep_kernel<<<dim3(2048 / 32, 512 / 32), dim3(32, 8)>>>(mlp_w1, w1_h, w1_l, 512, 2048);
    wprep_kernel<<<dim3(512 / 32, 2048 / 32), dim3(32, 8)>>>(mlp_w2, w2_h, w2_l, 2048, 512);
    // 1. adaLN scale/shift
    time_mlp_kernel<<<dim3(2 * DIM / 256, B_), 256>>>(t_emb, time_w, time_b);
    // 2. modulated LN1 -> bf16 hi/lo
    ln_kernel<1><<<NTOK, 128>>>(x, ln1_g, ln1_b, xh, xl);
    // 3. QKV GEMM -> fp32 qkv
    mma_gemm<0><<<dim3(12, NTOK / 128), 256, gemm_smem>>>(
        xh, xl, wq_h, wq_l, qkv_b, nullptr, qkv, nullptr, nullptr, 512, 1536);
    // 4. local attention (tensor cores) -> bf16 hi/lo
    attn_mma_kernel<<<dim3(NW, HEADS, B_), 128, attn_smem>>>(qkv, ah, al);
    // 5. proj + residual(x) -> fp32 y
    mma_gemm<1><<<dim3(4, NTOK / 128), 256, gemm_smem>>>(
        ah, al, wp_h, wp_l, proj_b, x, y, nullptr, nullptr, 512, 512);
    // 6. LN2 -> bf16 hi/lo
    ln_kernel<0><<<NTOK, 128>>>(y, ln2_g, ln2_b, xh, xl);
    // 7. MLP up + GELU -> bf16 hi/lo
    mma_gemm<2><<<dim3(16, NTOK / 128), 256, gemm_smem>>>(
        xh, xl, w1_h, w1_l, mlp_b1, nullptr, nullptr, fh, fl, 512, 2048);
    // 8. MLP down + residual(y) -> out
    mma_gemm<1><<<dim3(4, NTOK / 128), 256, gemm_smem>>>(
        fh, fl, w2_h, w2_l, mlp_b2, y, out, nullptr, nullptr, 2048, 512);
}